// round 16
// baseline (speedup 1.0000x reference)
#include <cuda_runtime.h>
#include <cuda_fp16.h>
#include <math.h>
#include <stdint.h>

#define N 8192
#define D 32
#define NB 64
#define B 128
#define GAMMA 0.03125f
#define REG 1e-3f
#define GRID_CHOL 148
#define NTHR 512
#define NTASK (NB * (NB + 1) / 2)
#define SPH 144u                 // half-K fp16 pitch (bytes)
#define BUFSZ 18432u             // 128 rows * 144
#define STG 73728u               // stage stride (4 buffers)
#define BOFF 36864u              // B buffers offset within stage
#define SC_OFF 147456u           // fp32 accumulator tile, pitch 132
#define CHOL_DYN 215040u         // SC_OFF + 128*528
#define SCL 64.f
#define ISCL (1.f / 4096.f)

// ---------------- device scratch ----------------
__device__ float g_A[(size_t)N * N];
__device__ float g_invL[(size_t)NB * B * B];
__device__ __align__(16) __half g_L0[(size_t)N * N];   // splits of 64*L
__device__ __align__(16) __half g_L1[(size_t)N * N];
__device__ __align__(16) __half g_W0[(size_t)NB * B * B]; // splits of 64*W
__device__ __align__(16) __half g_W1[(size_t)NB * B * B];
__device__ float g_xx[N];
__device__ float g_r[N];
__device__ float g_zsol[N];
__device__ float g_alpha[N];
// epoch-accumulating sync state
__device__ int g_tflag[NB * NB];
__device__ int g_dflag[NB];
__device__ int g_next;
__device__ int g_ecnt;
__device__ int g_ff[NB];
__device__ int g_fb[NB];
__device__ int g_fep;
__device__ int g_bep;

// ---------------- helpers ----------------
__device__ __forceinline__ uint32_t s2u(const void* p) {
    uint32_t a;
    asm("{ .reg .u64 t; cvta.to.shared.u64 t, %1; cvt.u32.u64 %0, t; }" : "=r"(a) : "l"(p));
    return a;
}
__device__ __forceinline__ void ldsm_x4(uint32_t* d, uint32_t addr) {
    asm volatile("ldmatrix.sync.aligned.m8n8.x4.shared.b16 {%0,%1,%2,%3}, [%4];"
        : "=r"(d[0]), "=r"(d[1]), "=r"(d[2]), "=r"(d[3]) : "r"(addr));
}
__device__ __forceinline__ void ldsm_x2(uint32_t* d, uint32_t addr) {
    asm volatile("ldmatrix.sync.aligned.m8n8.x2.shared.b16 {%0,%1}, [%2];"
        : "=r"(d[0]), "=r"(d[1]) : "r"(addr));
}
__device__ __forceinline__ void mma16816(float* c, const uint32_t* a, const uint32_t* b) {
    asm volatile("mma.sync.aligned.m16n8k16.row.col.f32.f16.f16.f32 "
        "{%0,%1,%2,%3}, {%4,%5,%6,%7}, {%8,%9}, {%0,%1,%2,%3};"
        : "+f"(c[0]), "+f"(c[1]), "+f"(c[2]), "+f"(c[3])
        : "r"(a[0]), "r"(a[1]), "r"(a[2]), "r"(a[3]), "r"(b[0]), "r"(b[1]));
}
__device__ __forceinline__ void cpasync16(uint32_t saddr, const void* g) {
    asm volatile("cp.async.cg.shared.global [%0], [%1], 16;" :: "r"(saddr), "l"(g));
}
__device__ __forceinline__ void split2(float x, __half& h0, __half& h1) {
    h0 = __float2half_rn(x);
    h1 = __float2half_rn(x - __half2float(h0));
}
__device__ __forceinline__ void tri_decode_row(int p, int& ti, int& tj) {
    float pf = sqrtf(8.f * (float)p + 1.f);
    int i = (int)((pf - 1.f) * 0.5f);
    while ((i + 1) * (i + 2) / 2 <= p) i++;
    while (i * (i + 1) / 2 > p) i--;
    ti = i; tj = p - i * (i + 1) / 2;
}
#define FBASE(j) ((j) * (2 * NB - (j) + 1) / 2)

__global__ void noop_kernel() {}

// ---------------- prep ----------------
__global__ void prep_kernel(const float* __restrict__ Xtr, const float* __restrict__ y) {
    int i = blockIdx.x * 256 + threadIdx.x;
    float s = 0.f;
#pragma unroll
    for (int dg = 0; dg < 8; dg++) {
        float4 v = *(const float4*)(Xtr + (size_t)i * D + dg * 4);
        s += v.x * v.x + v.y * v.y + v.z * v.z + v.w * v.w;
    }
    g_xx[i] = s;
    g_r[i] = y[i];
}

// ---------------- build gram (lower triangle of 128-blocks) ----------------
__global__ void __launch_bounds__(256, 2) build_kernel(const float* __restrict__ Xtr) {
    __shared__ float sXi[32 * 132];
    __shared__ float sXj[32 * 132];
    __shared__ float sxxi[128], sxxj[128];
    int tid = threadIdx.x;
    int bi, bj;
    tri_decode_row(blockIdx.x, bi, bj);

#pragma unroll
    for (int i = 0; i < 4; i++) {
        int f = tid + i * 256;
        int r = f >> 3;
        int dg = (f & 7) << 2;
        float4 v = *(const float4*)(Xtr + (size_t)(bi * B + r) * D + dg);
        sXi[(dg + 0) * 132 + r] = v.x; sXi[(dg + 1) * 132 + r] = v.y;
        sXi[(dg + 2) * 132 + r] = v.z; sXi[(dg + 3) * 132 + r] = v.w;
        float4 w = *(const float4*)(Xtr + (size_t)(bj * B + r) * D + dg);
        sXj[(dg + 0) * 132 + r] = w.x; sXj[(dg + 1) * 132 + r] = w.y;
        sXj[(dg + 2) * 132 + r] = w.z; sXj[(dg + 3) * 132 + r] = w.w;
    }
    if (tid < 128) { sxxi[tid] = g_xx[bi * B + tid]; sxxj[tid] = g_xx[bj * B + tid]; }
    __syncthreads();

    int tm = tid >> 4, tn = tid & 15;
    float acc[8][8];
#pragma unroll
    for (int i = 0; i < 8; i++)
#pragma unroll
        for (int j = 0; j < 8; j++) acc[i][j] = 0.f;

#pragma unroll
    for (int d = 0; d < 32; d++) {
        float a[8], b[8];
        *(float4*)(a)     = *(const float4*)(&sXi[d * 132 + tm * 8]);
        *(float4*)(a + 4) = *(const float4*)(&sXi[d * 132 + tm * 8 + 4]);
        *(float4*)(b)     = *(const float4*)(&sXj[d * 132 + tn * 8]);
        *(float4*)(b + 4) = *(const float4*)(&sXj[d * 132 + tn * 8 + 4]);
#pragma unroll
        for (int i = 0; i < 8; i++)
#pragma unroll
            for (int j = 0; j < 8; j++) acc[i][j] += a[i] * b[j];
    }

#pragma unroll
    for (int i = 0; i < 8; i++) {
        int li = tm * 8 + i;
        int gi = bi * B + li;
        float v[8];
#pragma unroll
        for (int j = 0; j < 8; j++) {
            int lj = tn * 8 + j;
            int gj = bj * B + lj;
            float sq = sxxi[li] + sxxj[lj] - 2.f * acc[i][j];
            sq = fmaxf(sq, 0.f);
            float val = __expf(-GAMMA * sq);
            if (gi == gj) val += REG;
            v[j] = val;
        }
        float* cp = g_A + (size_t)gi * N + bj * B + tn * 8;
        *(float4*)(cp)     = make_float4(v[0], v[1], v[2], v[3]);
        *(float4*)(cp + 4) = make_float4(v[4], v[5], v[6], v[7]);
    }
}

// ---------------- stage one half-K (64 cols) of panels i and j ----------------
__device__ __forceinline__ void stage_half(uint32_t dst,
                                           const __half* Li0, const __half* Li1,
                                           const __half* Lj0, const __half* Lj1,
                                           int k, int h, int tid) {
    size_t co = (size_t)k * B + h * 64;
#pragma unroll
    for (int q = 0; q < 8; q++) {
        int f = tid + (q << 9);
        int buf = f >> 10;
        int rem = f & 1023;
        int r = rem >> 3;
        int seg = rem & 7;
        const __half* p = (buf == 0) ? Li0 : (buf == 1) ? Li1 : (buf == 2) ? Lj0 : Lj1;
        cpasync16(dst + (uint32_t)buf * BUFSZ + (uint32_t)r * SPH + seg * 16,
                  p + (size_t)r * N + co + seg * 8);
    }
}

// ---------------- compute one half-K stage into acc ----------------
__device__ __forceinline__ void compute_half(uint32_t stg, int lane, int wm, int wn,
                                             float acc[2][4][4]) {
#pragma unroll
    for (int kt = 0; kt < 4; kt++) {
#pragma unroll
        for (int sb = 0; sb < 2; sb++) {
            uint32_t bfr[4][2];
#pragma unroll
            for (int nt = 0; nt < 4; nt++) {
                int n = wn * 32 + nt * 8 + (lane & 7);
                int col = kt * 16 + ((lane >> 3) & 1) * 8;
                ldsm_x2(bfr[nt], stg + BOFF + (uint32_t)sb * BUFSZ + (uint32_t)n * SPH + col * 2);
            }
#pragma unroll
            for (int sa = 0; sa < 2; sa++) {
                if (sa + sb > 1) continue;
                uint32_t af[2][4];
#pragma unroll
                for (int mt = 0; mt < 2; mt++) {
                    int rrow = wm * 32 + mt * 16 + (lane & 15);
                    int col = kt * 16 + (lane >> 4) * 8;
                    ldsm_x4(af[mt], stg + (uint32_t)sa * BUFSZ + (uint32_t)rrow * SPH + col * 2);
                }
#pragma unroll
                for (int mt = 0; mt < 2; mt++)
#pragma unroll
                    for (int nt = 0; nt < 4; nt++)
                        mma16816(acc[mt][nt], af[mt], bfr[nt]);
            }
        }
    }
}

// ---------------- potf core (sD pitch 129 holds M); writes invL + scaled W splits ----------------
__device__ void potf_core(int kb, float* sD, float* invd, float* rowbuf) {
    int tid = threadIdx.x;
    int tr = tid & 31, tj2 = tid >> 5;
    for (int c = 0; c < B - 1; c++) {
        float ipiv = __fdividef(1.f, sD[c * 129 + c]);
        for (int r = c + 1 + tr; r < B; r += 32) {
            float a = sD[r * 129 + c] * ipiv;
            for (int jj = c + 1 + tj2; jj <= r; jj += 16)
                sD[r * 129 + jj] -= a * sD[jj * 129 + c];
        }
        __syncthreads();
    }
    for (int c = tid; c < B; c += NTHR) invd[c] = rsqrtf(sD[c * 129 + c]);
    __syncthreads();
    for (int idx = tid; idx < B * B; idx += NTHR) {
        int r = idx >> 7, c = idx & 127;
        if (c < r) sD[r * 129 + c] *= invd[c];
        else if (c == r) sD[r * 129 + c] = invd[c];
    }
    __syncthreads();
    for (int r = 1; r < B; r++) {
        for (int c = tid; c < r; c += NTHR) rowbuf[c] = sD[r * 129 + c];
        __syncthreads();
        if (tid < r) {
            int c = tid;
            float a0 = 0.f, a1 = 0.f, a2 = 0.f, a3 = 0.f;
            int jj = c;
            for (; jj + 3 < r; jj += 4) {
                a0 += rowbuf[jj]     * sD[jj * 129 + c];
                a1 += rowbuf[jj + 1] * sD[(jj + 1) * 129 + c];
                a2 += rowbuf[jj + 2] * sD[(jj + 2) * 129 + c];
                a3 += rowbuf[jj + 3] * sD[(jj + 3) * 129 + c];
            }
            for (; jj < r; jj++) a0 += rowbuf[jj] * sD[jj * 129 + c];
            sD[r * 129 + c] = -invd[r] * ((a0 + a1) + (a2 + a3));
        }
        __syncthreads();
    }
    size_t koff = (size_t)kb * B * B;
    for (int idx = tid; idx < B * B; idx += NTHR) {
        int r = idx >> 7, c = idx & 127;
        float w = (c <= r) ? sD[r * 129 + c] : 0.f;
        g_invL[koff + idx] = w;
        __half h0, h1;
        split2(w * SCL, h0, h1);
        g_W0[koff + idx] = h0;
        g_W1[koff + idx] = h1;
    }
    __syncthreads();
}

// ---------------- persistent left-looking cholesky ----------------
__global__ void __launch_bounds__(NTHR, 1) chol_kernel() {
    extern __shared__ char dsm[];
    uint32_t sbase = s2u(dsm);
    float* sC = (float*)(dsm + SC_OFF);
    __shared__ float invd[128];
    __shared__ float rowbuf[128];
    __shared__ int s_t;
    __shared__ int s_e;

    int tid = threadIdx.x;
    int lane = tid & 31, warp = tid >> 5;
    int wm = warp & 3, wn = warp >> 2;

    if (tid == 0) s_e = atomicAdd(&g_ecnt, 1) / GRID_CHOL + 1;
    __syncthreads();
    int e = s_e;
    int base = (e - 1) * (NTASK + GRID_CHOL);

    volatile int* vtf = (volatile int*)g_tflag;
    volatile int* vdf = (volatile int*)g_dflag;

    while (true) {
        if (tid == 0) s_t = atomicAdd(&g_next, 1) - base;
        __syncthreads();
        int t = s_t;
        if (t >= NTASK) break;

        float disc = (2.f * NB + 1.f) * (2.f * NB + 1.f) - 8.f * (float)t;
        int j = (int)((2.f * NB + 1.f - sqrtf(disc)) * 0.5f);
        if (j > NB - 1) j = NB - 1;
        if (j < 0) j = 0;
        while (j < NB - 1 && FBASE(j + 1) <= t) j++;
        while (FBASE(j) > t) j--;
        int i = j + (t - FBASE(j));
        bool diag = (i == j);

        const __half* Li0 = g_L0 + (size_t)(i * B) * N;
        const __half* Li1 = g_L1 + (size_t)(i * B) * N;
        const __half* Lj0 = g_L0 + (size_t)(j * B) * N;
        const __half* Lj1 = g_L1 + (size_t)(j * B) * N;

        float acc[2][4][4];
#pragma unroll
        for (int mt = 0; mt < 2; mt++)
#pragma unroll
            for (int nt = 0; nt < 4; nt++)
#pragma unroll
                for (int x = 0; x < 4; x++) acc[mt][nt][x] = 0.f;
        bool flushed = false;

        // ---- k-stream: acc += (64 L(i,k)) * (64 L(j,k))^T ----
        for (int k = 0; k < j; k++) {
            if (tid == 0) {
                while (vtf[k * NB + i] < e) __nanosleep(32);
                if (!diag) while (vtf[k * NB + j] < e) __nanosleep(32);
            }
            __syncthreads();
            __threadfence();
            stage_half(sbase, Li0, Li1, Lj0, Lj1, k, 0, tid);
            asm volatile("cp.async.commit_group;");
            stage_half(sbase + STG, Li0, Li1, Lj0, Lj1, k, 1, tid);
            asm volatile("cp.async.commit_group;");
            asm volatile("cp.async.wait_group 1;" ::: "memory");
            __syncthreads();
            compute_half(sbase, lane, wm, wn, acc);
            asm volatile("cp.async.wait_group 0;" ::: "memory");
            __syncthreads();
            compute_half(sbase + STG, lane, wm, wn, acc);
            // periodic flush to fp32 smem accumulator (thread-exclusive slots)
            if ((k & 1) == 1) {
                bool was = flushed;
#pragma unroll
                for (int mt = 0; mt < 2; mt++)
#pragma unroll
                    for (int nt = 0; nt < 4; nt++) {
                        int lr = wm * 32 + mt * 16 + (lane >> 2);
                        int lc = wn * 32 + nt * 8 + (lane & 3) * 2;
                        int o0 = lr * 132 + lc, o1 = (lr + 8) * 132 + lc;
                        if (was) {
                            sC[o0] += acc[mt][nt][0]; sC[o0 + 1] += acc[mt][nt][1];
                            sC[o1] += acc[mt][nt][2]; sC[o1 + 1] += acc[mt][nt][3];
                        } else {
                            sC[o0] = acc[mt][nt][0]; sC[o0 + 1] = acc[mt][nt][1];
                            sC[o1] = acc[mt][nt][2]; sC[o1 + 1] = acc[mt][nt][3];
                        }
                        acc[mt][nt][0] = acc[mt][nt][1] = acc[mt][nt][2] = acc[mt][nt][3] = 0.f;
                    }
                flushed = true;
            }
            __syncthreads();
        }
        // combine: acc := 4096 * S
        if (flushed) {
#pragma unroll
            for (int mt = 0; mt < 2; mt++)
#pragma unroll
                for (int nt = 0; nt < 4; nt++) {
                    int lr = wm * 32 + mt * 16 + (lane >> 2);
                    int lc = wn * 32 + nt * 8 + (lane & 3) * 2;
                    acc[mt][nt][0] += sC[lr * 132 + lc];
                    acc[mt][nt][1] += sC[lr * 132 + lc + 1];
                    acc[mt][nt][2] += sC[(lr + 8) * 132 + lc];
                    acc[mt][nt][3] += sC[(lr + 8) * 132 + lc + 1];
                }
        }

        const float* G = g_A + (size_t)(i * B) * N + (size_t)j * B;

        if (diag) {
            float* sD = (float*)dsm;
#pragma unroll
            for (int mt = 0; mt < 2; mt++)
#pragma unroll
                for (int nt = 0; nt < 4; nt++) {
                    int col = wn * 32 + nt * 8 + (lane & 3) * 2;
#pragma unroll
                    for (int hh = 0; hh < 2; hh++) {
                        int r = wm * 32 + mt * 16 + (lane >> 2) + hh * 8;
                        float2 gg = *(const float2*)(G + (size_t)r * N + col);
                        sD[r * 129 + col]     = gg.x - acc[mt][nt][hh * 2] * ISCL;
                        sD[r * 129 + col + 1] = gg.y - acc[mt][nt][hh * 2 + 1] * ISCL;
                    }
                }
            __syncthreads();
            potf_core(j, sD, invd, rowbuf);
            __threadfence();
            __syncthreads();
            if (tid == 0) atomicAdd(&g_dflag[j], 1);
        } else {
            if (tid == 0) { while (vdf[j] < e) __nanosleep(32); }
            __syncthreads();
            __threadfence();
            size_t koff = (size_t)j * B * B;
#pragma unroll
            for (int q = 0; q < 8; q++) {
                int f = tid + (q << 9);
                int h = f >> 11;
                int rem = f & 2047;
                int sp = rem >> 10;
                int r2 = (rem >> 3) & 127;
                int seg = rem & 7;
                const __half* w = sp ? (g_W1 + koff) : (g_W0 + koff);
                cpasync16(sbase + (uint32_t)h * STG + BOFF + (uint32_t)sp * BUFSZ +
                          (uint32_t)r2 * SPH + seg * 16,
                          w + (size_t)r2 * B + h * 64 + seg * 8);
            }
            asm volatile("cp.async.commit_group;");
            // M = G - S ; store splits of 64*M into A buffers of both stages
#pragma unroll
            for (int mt = 0; mt < 2; mt++)
#pragma unroll
                for (int nt = 0; nt < 4; nt++) {
                    int col = wn * 32 + nt * 8 + (lane & 3) * 2;
                    int s = col >> 6;
                    int c = col & 63;
#pragma unroll
                    for (int hh = 0; hh < 2; hh++) {
                        int r = wm * 32 + mt * 16 + (lane >> 2) + hh * 8;
                        float2 gg = *(const float2*)(G + (size_t)r * N + col);
                        float m0 = (gg.x - acc[mt][nt][hh * 2] * ISCL) * SCL;
                        float m1 = (gg.y - acc[mt][nt][hh * 2 + 1] * ISCL) * SCL;
                        __half a0, a1, b0, b1;
                        split2(m0, a0, a1); split2(m1, b0, b1);
                        *(__half2*)(dsm + (uint32_t)s * STG + (uint32_t)r * SPH + c * 2) =
                            __halves2half2(a0, b0);
                        *(__half2*)(dsm + (uint32_t)s * STG + BUFSZ + (uint32_t)r * SPH + c * 2) =
                            __halves2half2(a1, b1);
                    }
                }
            asm volatile("cp.async.wait_group 0;" ::: "memory");
            __syncthreads();
#pragma unroll
            for (int mt = 0; mt < 2; mt++)
#pragma unroll
                for (int nt = 0; nt < 4; nt++)
#pragma unroll
                    for (int x = 0; x < 4; x++) acc[mt][nt][x] = 0.f;
            compute_half(sbase, lane, wm, wn, acc);
            compute_half(sbase + STG, lane, wm, wn, acc);
            __syncthreads();
            // epilogue: P = acc/4096 -> sC staging -> coalesced fp32 + scaled splits
#pragma unroll
            for (int mt = 0; mt < 2; mt++)
#pragma unroll
                for (int nt = 0; nt < 4; nt++) {
                    int lr = wm * 32 + mt * 16 + (lane >> 2);
                    int lc = wn * 32 + nt * 8 + (lane & 3) * 2;
                    sC[lr * 132 + lc]           = acc[mt][nt][0] * ISCL;
                    sC[lr * 132 + lc + 1]       = acc[mt][nt][1] * ISCL;
                    sC[(lr + 8) * 132 + lc]     = acc[mt][nt][2] * ISCL;
                    sC[(lr + 8) * 132 + lc + 1] = acc[mt][nt][3] * ISCL;
                }
            __syncthreads();
#pragma unroll
            for (int q = 0; q < 8; q++) {
                int f = tid + (q << 9);
                int r = f >> 5;
                int c4 = (f & 31) * 4;
                float4 s = *(float4*)(sC + r * 132 + c4);
                size_t off = (size_t)(i * B + r) * N + (size_t)j * B + c4;
                *(float4*)(g_A + off) = s;
                __half x0, x1, y0, y1, z0, z1, w0, w1;
                split2(s.x * SCL, x0, x1); split2(s.y * SCL, y0, y1);
                split2(s.z * SCL, z0, z1); split2(s.w * SCL, w0, w1);
                *(__half2*)(g_L0 + off)     = __halves2half2(x0, y0);
                *(__half2*)(g_L0 + off + 2) = __halves2half2(z0, w0);
                *(__half2*)(g_L1 + off)     = __halves2half2(x1, y1);
                *(__half2*)(g_L1 + off + 2) = __halves2half2(z1, w1);
            }
            __threadfence();
            __syncthreads();
            if (tid == 0) atomicAdd(&g_tflag[j * NB + i], 1);
        }
        __syncthreads();
    }
}

// ---------------- spin-chained forward solve (epoch-safe) ----------------
__global__ void __launch_bounds__(512, 1) fwd_solve() {
    int k = blockIdx.x;
    int tid = threadIdx.x;
    int t = tid & 127, q = tid >> 7;
    __shared__ float svec[128];
    __shared__ float red[512];
    __shared__ int s_e;
    if (tid == 0) s_e = atomicAdd(&g_fep, 1) / NB + 1;
    __syncthreads();
    int e = s_e;
    float acc = (q == 0) ? g_r[k * B + t] : 0.f;
    for (int j = 0; j < k; j++) {
        if (tid == 0) { while (((volatile int*)g_ff)[j] < e) __nanosleep(32); }
        __syncthreads();
        __threadfence();
        if (tid < 128) svec[tid] = g_zsol[j * B + tid];
        __syncthreads();
        const float* Lr = g_A + (size_t)(k * B + t) * N + (size_t)j * B + q * 32;
        float a0 = 0.f, a1 = 0.f;
#pragma unroll
        for (int c = 0; c < 32; c += 8) {
            float4 l0 = *(const float4*)(Lr + c);
            float4 l1 = *(const float4*)(Lr + c + 4);
            int cc = q * 32 + c;
            a0 += l0.x * svec[cc] + l0.y * svec[cc + 1] + l0.z * svec[cc + 2] + l0.w * svec[cc + 3];
            a1 += l1.x * svec[cc + 4] + l1.y * svec[cc + 5] + l1.z * svec[cc + 6] + l1.w * svec[cc + 7];
        }
        acc -= a0 + a1;
        __syncthreads();
    }
    red[q * 128 + t] = acc;
    __syncthreads();
    if (tid < 128) svec[tid] = red[tid] + red[128 + tid] + red[256 + tid] + red[384 + tid];
    __syncthreads();
    const float* Wr = g_invL + (size_t)k * B * B + (size_t)t * B + q * 32;
    float z = 0.f;
#pragma unroll
    for (int c = 0; c < 32; c += 4) {
        float4 w = *(const float4*)(Wr + c);
        int cc = q * 32 + c;
        z += w.x * svec[cc] + w.y * svec[cc + 1] + w.z * svec[cc + 2] + w.w * svec[cc + 3];
    }
    red[q * 128 + t] = z;
    __syncthreads();
    if (tid < 128) g_zsol[k * B + tid] = red[tid] + red[128 + tid] + red[256 + tid] + red[384 + tid];
    __threadfence();
    __syncthreads();
    if (tid == 0) atomicAdd(&g_ff[k], 1);
}

// ---------------- spin-chained backward solve (epoch-safe) ----------------
__global__ void __launch_bounds__(512, 1) bwd_solve() {
    int k = NB - 1 - blockIdx.x;
    int tid = threadIdx.x;
    int t = tid & 127, q = tid >> 7;
    __shared__ float svec[128];
    __shared__ float red[512];
    __shared__ int s_e;
    if (tid == 0) s_e = atomicAdd(&g_bep, 1) / NB + 1;
    __syncthreads();
    int e = s_e;
    float acc = (q == 0) ? g_zsol[k * B + t] : 0.f;
    for (int j = k + 1; j < NB; j++) {
        if (tid == 0) { while (((volatile int*)g_fb)[j] < e) __nanosleep(32); }
        __syncthreads();
        __threadfence();
        if (tid < 128) svec[tid] = g_alpha[j * B + tid];
        __syncthreads();
        const float* Lc = g_A + (size_t)(j * B + q * 32) * N + (size_t)k * B + t;
        float a0 = 0.f, a1 = 0.f, a2 = 0.f, a3 = 0.f;
#pragma unroll
        for (int r = 0; r < 32; r += 4) {
            int rr = q * 32 + r;
            a0 += Lc[(size_t)(r + 0) * N] * svec[rr + 0];
            a1 += Lc[(size_t)(r + 1) * N] * svec[rr + 1];
            a2 += Lc[(size_t)(r + 2) * N] * svec[rr + 2];
            a3 += Lc[(size_t)(r + 3) * N] * svec[rr + 3];
        }
        acc -= ((a0 + a1) + (a2 + a3));
        __syncthreads();
    }
    red[q * 128 + t] = acc;
    __syncthreads();
    if (tid < 128) svec[tid] = red[tid] + red[128 + tid] + red[256 + tid] + red[384 + tid];
    __syncthreads();
    const float* Wc = g_invL + (size_t)k * B * B + (size_t)(q * 32) * B + t;
    float al = 0.f;
#pragma unroll 8
    for (int r = 0; r < 32; r++) al += Wc[(size_t)r * B] * svec[q * 32 + r];
    red[q * 128 + t] = al;
    __syncthreads();
    if (tid < 128) g_alpha[k * B + tid] = red[tid] + red[128 + tid] + red[256 + tid] + red[384 + tid];
    __threadfence();
    __syncthreads();
    if (tid == 0) atomicAdd(&g_fb[k], 1);
}

// ---------------- fused predict ----------------
__global__ void __launch_bounds__(256, 2) predict_kernel(const float* __restrict__ Xte,
                                                         const float* __restrict__ Xtr,
                                                         float* __restrict__ out) {
    __shared__ float sTr[32 * 132];
    __shared__ float sAl[128], sXX[128];
    __shared__ float sRed[256];
    int tid = threadIdx.x;
    int rl = tid >> 3, sl = tid & 7;
    int grow = blockIdx.x * 32 + rl;

    float xt[32];
#pragma unroll
    for (int dg = 0; dg < 8; dg++)
        *(float4*)(xt + dg * 4) = *(const float4*)(Xte + (size_t)grow * D + dg * 4);
    float xxt = 0.f;
#pragma unroll
    for (int d = 0; d < 32; d++) xxt += xt[d] * xt[d];

    float acc = 0.f;
    for (int ch = 0; ch < N / 128; ch++) {
        int pbase = ch * 128;
        __syncthreads();
#pragma unroll
        for (int i = 0; i < 4; i++) {
            int f = tid + i * 256;
            int p = f >> 3;
            int dg = (f & 7) << 2;
            float4 v = *(const float4*)(Xtr + (size_t)(pbase + p) * D + dg);
            sTr[(dg + 0) * 132 + p] = v.x; sTr[(dg + 1) * 132 + p] = v.y;
            sTr[(dg + 2) * 132 + p] = v.z; sTr[(dg + 3) * 132 + p] = v.w;
        }
        if (tid < 128) { sAl[tid] = g_alpha[pbase + tid]; sXX[tid] = g_xx[pbase + tid]; }
        __syncthreads();
#pragma unroll 4
        for (int i = 0; i < 16; i++) {
            int p = i * 8 + sl;
            float dot = 0.f;
#pragma unroll
            for (int d = 0; d < 32; d++) dot += xt[d] * sTr[d * 132 + p];
            float sq = fmaxf(xxt + sXX[p] - 2.f * dot, 0.f);
            acc += __expf(-GAMMA * sq) * sAl[p];
        }
    }
    sRed[rl * 8 + sl] = acc;
    __syncthreads();
    if (tid < 32) {
        float s = 0.f;
#pragma unroll
        for (int j = 0; j < 8; j++) s += sRed[tid * 8 + j];
        out[blockIdx.x * 32 + tid] = s;
    }
}

// ---------------- launcher ----------------
extern "C" void kernel_launch(void* const* d_in, const int* in_sizes, int n_in,
                              void* d_out, int out_size) {
    const float* Xtr = (const float*)d_in[0];
    const float* y   = (const float*)d_in[1];
    const float* Xte = (const float*)d_in[2];
    float* out = (float*)d_out;

    cudaFuncSetAttribute(chol_kernel, cudaFuncAttributeMaxDynamicSharedMemorySize, CHOL_DYN);

    prep_kernel<<<N / 256, 256>>>(Xtr, y);
    build_kernel<<<NTASK, 256>>>(Xtr);
    noop_kernel<<<1, 1>>>();
    chol_kernel<<<GRID_CHOL, NTHR, CHOL_DYN>>>();
    fwd_solve<<<NB, 512>>>();
    bwd_solve<<<NB, 512>>>();
    predict_kernel<<<N / 32, 256>>>(Xte, Xtr, out);
}